// round 1
// baseline (speedup 1.0000x reference)
#include <cuda_runtime.h>
#include <stdint.h>

// decoder_11218454577221: per-edge head-weighted pairwise distance -> reciprocal-square
// cluster scores.  score[e,c] = 1 / ((dist[e] - m[c])^2 + b)
//
// Strategy: warp-cooperative gather (one warp loads a full 512B node row,
// lane j = float4 j), shfl reductions for per-head norms and head sum,
// fully coalesced 128B output row per edge (lane = cluster index).

#define EPSF 1e-4f

__device__ float g_wsm[8];   // softmax(w)
__device__ float g_m[32];    // relu(cumsum(|r+eps|+eps))
__device__ float g_b;        // b scalar
__device__ int   g_is64;     // 1 if src/dst are int64, 0 if int32

// ---------------------------------------------------------------------------
// Prep: softmax weights, cluster means, b, and index-dtype detection.
// Single thread; trivially cheap vs main kernel.
// ---------------------------------------------------------------------------
__global__ void prep_kernel(const float* __restrict__ w,
                            const float* __restrict__ r,
                            const float* __restrict__ b,
                            const void*  __restrict__ src,
                            const void*  __restrict__ dst,
                            int E)
{
    // softmax over 8 head weights
    float wmax = w[0];
#pragma unroll
    for (int i = 1; i < 8; i++) wmax = fmaxf(wmax, w[i]);
    float ex[8];
    float s = 0.0f;
#pragma unroll
    for (int i = 0; i < 8; i++) { ex[i] = expf(w[i] - wmax); s += ex[i]; }
    float inv = 1.0f / s;
#pragma unroll
    for (int i = 0; i < 8; i++) g_wsm[i] = ex[i] * inv;

    // cumulative cluster means, relu
    float cum = 0.0f;
    for (int c = 0; c < 32; c++) {
        cum += fabsf(r[c] + EPSF) + EPSF;
        g_m[c] = fmaxf(cum, 0.0f);
    }
    g_b = b[0];

    // Detect index width: jax default config degrades jnp.int64 -> int32.
    // If data is true int64 (values < 2^31), every odd 32-bit word is 0.
    const int* s32 = (const int*)src;
    const int* d32 = (const int*)dst;
    int n = (E < 16) ? E : 16;
    int all0 = 1;
    for (int k = 0; k < n; k++) {
        if (s32[2 * k + 1] != 0) all0 = 0;
        if (d32[2 * k + 1] != 0) all0 = 0;
    }
    g_is64 = all0;
}

// ---------------------------------------------------------------------------
// Main kernel: each warp owns 32 consecutive edges.  For each edge the full
// warp gathers both node rows coalesced (float4 per lane = 512B row), reduces
// per-head sumsq with shfl_xor(1,2), applies sqrt * softmax weight, reduces
// across the 8 head groups with shfl_xor(4,8,16), then writes the 32 cluster
// scores as one coalesced 128B row (lane = c).
// ---------------------------------------------------------------------------
__global__ __launch_bounds__(256)
void edge_kernel(const float4* __restrict__ h4,
                 const void* __restrict__ src,
                 const void* __restrict__ dst,
                 float* __restrict__ out,
                 int E)
{
    const int lane = threadIdx.x & 31;
    const int warp = (blockIdx.x * blockDim.x + threadIdx.x) >> 5;
    const int base = warp << 5;
    if (base >= E) return;

    const int my_e = base + lane;
    int sv = 0, dv = 0;
    if (my_e < E) {
        if (g_is64) {
            sv = (int)((const long long*)src)[my_e];
            dv = (int)((const long long*)dst)[my_e];
        } else {
            sv = ((const int*)src)[my_e];
            dv = ((const int*)dst)[my_e];
        }
    }

    const float wsm   = g_wsm[lane >> 2];  // head = lane/4
    const float mlane = g_m[lane];         // cluster mean for this lane's c
    const float bval  = g_b;

    const int cnt = min(32, E - base);

#pragma unroll 4
    for (int i = 0; i < cnt; i++) {
        const int s = __shfl_sync(0xffffffffu, sv, i);
        const int d = __shfl_sync(0xffffffffu, dv, i);

        // coalesced row gather: warp covers the full 128-float row
        float4 a = h4[(size_t)s * 32 + lane];
        float4 c = h4[(size_t)d * 32 + lane];

        float dx = a.x - c.x;
        float dy = a.y - c.y;
        float dz = a.z - c.z;
        float dw = a.w - c.w;
        float ss = dx * dx;
        ss = fmaf(dy, dy, ss);
        ss = fmaf(dz, dz, ss);
        ss = fmaf(dw, dw, ss);

        // reduce the 4 lanes of each head group -> per-head sum of squares
        ss += __shfl_xor_sync(0xffffffffu, ss, 1);
        ss += __shfl_xor_sync(0xffffffffu, ss, 2);

        // weighted per-head norm, then sum across the 8 head groups
        float v = sqrtf(ss) * wsm;
        v += __shfl_xor_sync(0xffffffffu, v, 4);
        v += __shfl_xor_sync(0xffffffffu, v, 8);
        v += __shfl_xor_sync(0xffffffffu, v, 16);
        // v == dist[e] on every lane

        float t = v - mlane;
        out[(size_t)(base + i) * 32 + lane] = __fdividef(1.0f, fmaf(t, t, bval));
    }
}

// ---------------------------------------------------------------------------
// kernel_launch: inputs per reference order:
//   0: h      float32 [N, H, D]   (N*128 floats)
//   1: w      float32 [H]
//   2: r_dist float32 [1, C]
//   3: b      float32 [1]
//   4: src    int64/int32 [E]
//   5: dst    int64/int32 [E]
// out: float32 [E, C]
// ---------------------------------------------------------------------------
extern "C" void kernel_launch(void* const* d_in, const int* in_sizes, int n_in,
                              void* d_out, int out_size)
{
    const float* h = (const float*)d_in[0];
    const float* w = (const float*)d_in[1];
    const float* r = (const float*)d_in[2];
    const float* b = (const float*)d_in[3];
    const void*  src = d_in[4];
    const void*  dst = d_in[5];
    const int E = in_sizes[4];

    prep_kernel<<<1, 1>>>(w, r, b, src, dst, E);

    const int warps  = (E + 31) / 32;
    const int blocks = (warps + 7) / 8;   // 8 warps (256 threads) per block
    edge_kernel<<<blocks, 256>>>((const float4*)h, src, dst, (float*)d_out, E);
}

// round 2
// speedup vs baseline: 1.3452x; 1.3452x over previous
#include <cuda_runtime.h>
#include <stdint.h>

// decoder_11218454577221
// score[e,c] = 1 / ((dist[e] - m[c])^2 + b),  dist[e] = sum_h softmax(w)_h * ||h[dst]-h[src]||_h
//
// Round 2: half-warp-per-edge mapping. 16 lanes own one edge; each lane loads
// float4 l and l+16 of both node rows (heads g and g+4), reducing per-edge MIO
// ops from ~16 to ~12.5 (gather wavefronts are irreducible at 8/edge in fp32).

#define EPSF 1e-4f

__device__ float g_wsm[8];   // softmax(w)
__device__ float g_m[32];    // relu(cumsum(|r+eps|+eps))
__device__ float g_b;        // b scalar
__device__ int   g_is64;     // 1 if src/dst are int64, 0 if int32

// ---------------------------------------------------------------------------
__global__ void prep_kernel(const float* __restrict__ w,
                            const float* __restrict__ r,
                            const float* __restrict__ b,
                            const void*  __restrict__ src,
                            const void*  __restrict__ dst,
                            int E)
{
    float wmax = w[0];
#pragma unroll
    for (int i = 1; i < 8; i++) wmax = fmaxf(wmax, w[i]);
    float ex[8];
    float s = 0.0f;
#pragma unroll
    for (int i = 0; i < 8; i++) { ex[i] = expf(w[i] - wmax); s += ex[i]; }
    float inv = 1.0f / s;
#pragma unroll
    for (int i = 0; i < 8; i++) g_wsm[i] = ex[i] * inv;

    float cum = 0.0f;
    for (int c = 0; c < 32; c++) {
        cum += fabsf(r[c] + EPSF) + EPSF;
        g_m[c] = fmaxf(cum, 0.0f);
    }
    g_b = b[0];

    // int64 vs int32 detection: true int64 indices (< 2^31) have zero odd words.
    const int* s32 = (const int*)src;
    const int* d32 = (const int*)dst;
    int n = (E < 16) ? E : 16;
    int all0 = 1;
    for (int k = 0; k < n; k++) {
        if (s32[2 * k + 1] != 0) all0 = 0;
        if (d32[2 * k + 1] != 0) all0 = 0;
    }
    g_is64 = all0;
}

// ---------------------------------------------------------------------------
// Each warp owns 32 consecutive edges; per iteration it processes 2 edges
// (lanes 0-15 -> edge 2i, lanes 16-31 -> edge 2i+1).
// Per half-lane hl (0..15):
//   loads float4 hl and hl+16 of src row and dst row (32-bit byte offsets)
//   ss0 = partial sumsq of head g=hl>>2, ss1 = head g+4
//   xor1/xor2 reduce both; v = sqrt(ss0)*w_g + sqrt(ss1)*w_{g+4}
//   xor4/xor8 sum the 4 head-pair groups -> dist on all 16 lanes
//   writes clusters (2*hl, 2*hl+1) as one float2 -> 256B contiguous per 2 edges
// ---------------------------------------------------------------------------
__global__ __launch_bounds__(256)
void edge_kernel(const char* __restrict__ hbase,
                 const void* __restrict__ src,
                 const void* __restrict__ dst,
                 char* __restrict__ outbase,
                 int E)
{
    __shared__ int2 sidx[8][32];

    const int lane = threadIdx.x & 31;
    const int wIdx = threadIdx.x >> 5;
    const int warp = (blockIdx.x * blockDim.x + threadIdx.x) >> 5;
    const int base = warp << 5;
    if (base >= E) return;

    // stage this warp's 32 (src,dst) pairs into shared memory
    {
        const int my_e = base + lane;
        const int e_cl = (my_e < E) ? my_e : (E - 1);
        int sv, dv;
        if (g_is64) {
            sv = (int)((const long long*)src)[e_cl];
            dv = (int)((const long long*)dst)[e_cl];
        } else {
            sv = ((const int*)src)[e_cl];
            dv = ((const int*)dst)[e_cl];
        }
        sidx[wIdx][lane] = make_int2(sv, dv);
    }
    __syncwarp();

    const int half = lane >> 4;        // which edge of the pair
    const int hl   = lane & 15;        // lane within half
    const unsigned hoff = (unsigned)hl * 16u;

    const float wg0 = g_wsm[hl >> 2];
    const float wg1 = g_wsm[(hl >> 2) + 4];
    const float m0  = g_m[2 * hl];
    const float m1  = g_m[2 * hl + 1];
    const float bv  = g_b;

    const bool full = (base + 32 <= E);

#pragma unroll 2
    for (int i = 0; i < 16; i++) {
        const int e = base + 2 * i + half;
        const int2 p = sidx[wIdx][2 * i + half];

        const unsigned offS = (unsigned)p.x * 512u + hoff;
        const unsigned offD = (unsigned)p.y * 512u + hoff;

        const float4 a0 = *(const float4*)(hbase + offS);
        const float4 a1 = *(const float4*)(hbase + offS + 256u);
        const float4 c0 = *(const float4*)(hbase + offD);
        const float4 c1 = *(const float4*)(hbase + offD + 256u);

        float dx, dy, dz, dw;
        dx = a0.x - c0.x; dy = a0.y - c0.y; dz = a0.z - c0.z; dw = a0.w - c0.w;
        float ss0 = dx * dx;
        ss0 = fmaf(dy, dy, ss0); ss0 = fmaf(dz, dz, ss0); ss0 = fmaf(dw, dw, ss0);

        dx = a1.x - c1.x; dy = a1.y - c1.y; dz = a1.z - c1.z; dw = a1.w - c1.w;
        float ss1 = dx * dx;
        ss1 = fmaf(dy, dy, ss1); ss1 = fmaf(dz, dz, ss1); ss1 = fmaf(dw, dw, ss1);

        // reduce each head partial over its 4-lane group (stays within halves)
        ss0 += __shfl_xor_sync(0xffffffffu, ss0, 1);
        ss1 += __shfl_xor_sync(0xffffffffu, ss1, 1);
        ss0 += __shfl_xor_sync(0xffffffffu, ss0, 2);
        ss1 += __shfl_xor_sync(0xffffffffu, ss1, 2);

        // weighted head norms, then sum the 4 head-pair groups
        float v = fmaf(sqrtf(ss0), wg0, sqrtf(ss1) * wg1);
        v += __shfl_xor_sync(0xffffffffu, v, 4);
        v += __shfl_xor_sync(0xffffffffu, v, 8);
        // v == dist[e] on all 16 lanes of this half

        const float t0 = v - m0;
        const float t1 = v - m1;
        float2 o;
        o.x = __fdividef(1.0f, fmaf(t0, t0, bv));
        o.y = __fdividef(1.0f, fmaf(t1, t1, bv));

        if (full || e < E) {
            *(float2*)(outbase + (unsigned)e * 128u + (unsigned)hl * 8u) = o;
        }
    }
}

// ---------------------------------------------------------------------------
// inputs: 0:h f32[N,H,D]  1:w f32[H]  2:r f32[1,C]  3:b f32[1]
//         4:src int[E]    5:dst int[E]      out: f32[E,C]
// ---------------------------------------------------------------------------
extern "C" void kernel_launch(void* const* d_in, const int* in_sizes, int n_in,
                              void* d_out, int out_size)
{
    const float* h = (const float*)d_in[0];
    const float* w = (const float*)d_in[1];
    const float* r = (const float*)d_in[2];
    const float* b = (const float*)d_in[3];
    const void*  src = d_in[4];
    const void*  dst = d_in[5];
    const int E = in_sizes[4];

    prep_kernel<<<1, 1>>>(w, r, b, src, dst, E);

    const int warps  = (E + 31) / 32;
    const int blocks = (warps + 7) / 8;
    edge_kernel<<<blocks, 256>>>((const char*)h, src, dst, (char*)d_out, E);
}